// round 1
// baseline (speedup 1.0000x reference)
#include <cuda_runtime.h>
#include <cuda_bf16.h>
#include <mma.h>

using namespace nvcuda;

#define B_   4096
#define K_   1024
#define NG   4096    /* 4*H */
#define H_   1024
#define NM   4

#define BROWS 32     /* batch rows per CTA (x4 planes -> M=128) */
#define BM    128
#define BN    128
#define BK    32
#define LDA   40     /* bf16 elems; 80B rows, 16B-multiple */
#define LDB   136    /* bf16 elems; 272B rows, 16B-multiple */
#define NTHREADS 256

// ---- scratch (device globals; no runtime allocation) ----
__device__ __nv_bfloat16 g_yA[2][NM][B_][K_];   // 64 MB  quantized bit-plane ints (as bf16)
__device__ __nv_bfloat16 g_W[2][K_][NG];        // 16 MB  quantized weight ints (as bf16)
__device__ float         g_bias[2][NG];         //        bias ints
__device__ float         g_part[B_][NG];        // 64 MB  part1 (+part2) gates

// literal PACT: sign(x)*0.5*(|x| - ||x|-a| + a)  -- must match JAX op-for-op
__device__ __forceinline__ float pact_f(float x, float a) {
    float ax = fabsf(x);
    float t  = fabsf(ax - a);
    float s  = (x > 0.f) ? 0.5f : ((x < 0.f) ? -0.5f : 0.f);
    return s * ((ax - t) + a);
}

// quant_raw(x, 8, r) = round(clip(x/r, +-127/128)*128)/128*r
__device__ __forceinline__ float qr8(float x, float r) {
    float xs = x / r;
    xs = fminf(fmaxf(xs, -0.9921875f), 0.9921875f);
    return (rintf(xs * 128.f) * 0.0078125f) * r;
}

__device__ __forceinline__ float sigmoidf_(float x) {
    return 1.f / (1.f + expf(-x));
}

// ---------------- activation bit-split ----------------
__global__ void quant_acts_kernel(const float* __restrict__ input,
                                  const float* __restrict__ hx,
                                  const float* __restrict__ a1p,
                                  const float* __restrict__ a11p) {
    int idx = blockIdx.x * blockDim.x + threadIdx.x;
    if (idx >= 2 * B_ * K_) return;
    int branch = idx >> 22;            // B_*K_ = 2^22
    int e      = idx & (B_ * K_ - 1);
    float a = branch ? *a11p : *a1p;
    float x = branch ? hx[e] : input[e];
    float xv = pact_f(x, a) / a;
    float beta = 1.f;
#pragma unroll
    for (int m = 0; m < NM; m++) {
        float s = xv / beta;
        s = fminf(fmaxf(s, -0.9921875f), 0.9921875f);
        float yi = rintf(s * 128.f);          // integer in [-127,127]
        float y  = yi * 0.0078125f;
        xv = xv - y * beta;
        (&g_yA[branch][m][0][0])[e] = __float2bfloat16(yi);  // exact small int
        beta *= 0.5f;
    }
}

// ---------------- weight / bias quant ----------------
__global__ void quant_w_kernel(const float* __restrict__ wih,
                               const float* __restrict__ whh,
                               const float* __restrict__ bih,
                               const float* __restrict__ bhh) {
    int idx = blockIdx.x * blockDim.x + threadIdx.x;
    if (idx >= 2 * K_ * NG) return;
    int branch = idx >> 22;            // K_*NG = 2^22
    int e      = idx & (K_ * NG - 1);
    const float* w = branch ? whh : wih;
    float v = fminf(fmaxf(w[e], -0.9921875f), 0.9921875f);
    (&g_W[branch][0][0])[e] = __float2bfloat16(rintf(v * 128.f));
    if (e < NG) {
        const float* b = branch ? bhh : bih;
        float bv = fminf(fmaxf(b[e], -0.9921875f), 0.9921875f);
        g_bias[branch][e] = rintf(bv * 128.f);
    }
}

// ---------------- GEMM: 4 planes per CTA, bias-seeded accumulators ----------------
__global__ void __launch_bounds__(NTHREADS) gemm_kernel(int branch,
                                                        const float* __restrict__ ascale,
                                                        int accumulate) {
    __shared__ __align__(128) union {
        float btile[16][BN];                                   // 8 KB  (prologue)
        struct { __nv_bfloat16 A[BM][LDA]; __nv_bfloat16 Bt[BK][LDB]; } t;  // 18.5 KB (mainloop)
        float buf[4][32][68];                                  // 34 KB (epilogue)
    } sm;

    int tid    = threadIdx.x;
    int warp   = tid >> 5;
    int warp_m = warp >> 1;      // 0..3 == plane
    int warp_n = warp & 1;       // 0..1
    int n0 = blockIdx.x * BN;
    int b0 = blockIdx.y * BROWS;
    float a = *ascale;

    // accumulator init tile: every row = 128*b_int[col]
    for (int i = tid; i < 16 * BN; i += NTHREADS)
        sm.btile[i >> 7][i & 127] = 128.f * g_bias[branch][n0 + (i & 127)];
    __syncthreads();

    wmma::fragment<wmma::accumulator, 16, 16, 16, float> c[2][4];
#pragma unroll
    for (int i = 0; i < 2; i++)
#pragma unroll
        for (int j = 0; j < 4; j++)
            wmma::load_matrix_sync(c[i][j], &sm.btile[0][warp_n * 64 + j * 16],
                                   BN, wmma::mem_row_major);
    __syncthreads();

    // global pointers for this thread's load slots
    int arow   = tid >> 1;                 // 0..127 : M row
    int aseg   = (tid & 1) * 16;
    int aplane = arow >> 5;
    int agrow  = b0 + (arow & 31);
    const __nv_bfloat16* agp = &g_yA[branch][0][0][0] +
                               ((size_t)aplane * B_ + agrow) * K_ + aseg;
    int brow = tid >> 3;                   // 0..31 : K row
    int bseg = (tid & 7) * 16;
    const __nv_bfloat16* bgp = &g_W[branch][0][0] + (size_t)brow * NG + n0 + bseg;

    for (int kk = 0; kk < K_; kk += BK) {
        uint4 av0 = *(const uint4*)(agp + kk);
        uint4 av1 = *(const uint4*)(agp + kk + 8);
        uint4 bv0 = *(const uint4*)(bgp + (size_t)kk * NG);
        uint4 bv1 = *(const uint4*)(bgp + (size_t)kk * NG + 8);
        *(uint4*)&sm.t.A[arow][aseg]      = av0;
        *(uint4*)&sm.t.A[arow][aseg + 8]  = av1;
        *(uint4*)&sm.t.Bt[brow][bseg]     = bv0;
        *(uint4*)&sm.t.Bt[brow][bseg + 8] = bv1;
        __syncthreads();
#pragma unroll
        for (int ks = 0; ks < BK; ks += 16) {
            wmma::fragment<wmma::matrix_a, 16, 16, 16, __nv_bfloat16, wmma::row_major> af[2];
            wmma::fragment<wmma::matrix_b, 16, 16, 16, __nv_bfloat16, wmma::row_major> bf[4];
#pragma unroll
            for (int i = 0; i < 2; i++)
                wmma::load_matrix_sync(af[i], &sm.t.A[warp_m * 32 + i * 16][ks], LDA);
#pragma unroll
            for (int j = 0; j < 4; j++)
                wmma::load_matrix_sync(bf[j], &sm.t.Bt[ks][warp_n * 64 + j * 16], LDB);
#pragma unroll
            for (int i = 0; i < 2; i++)
#pragma unroll
                for (int j = 0; j < 4; j++)
                    wmma::mma_sync(c[i][j], af[i], bf[j], c[i][j]);
        }
        __syncthreads();
    }

    // per-plane quantize (acc/128 is an exact int + bias already folded in),
    // scale by a*beta_p/128, all exact powers of two
    float scale = (a * 0.0078125f) / (float)(1 << warp_m);
#pragma unroll
    for (int i = 0; i < 2; i++)
#pragma unroll
        for (int j = 0; j < 4; j++)
#pragma unroll
            for (int e = 0; e < c[i][j].num_elements; e++) {
                float q = rintf(c[i][j].x[e] * 0.0078125f);
                q = fminf(fmaxf(q, -127.f), 127.f);
                c[i][j].x[e] = q * scale;
            }

    // combine 4 planes across warps via smem, two 64-col rounds
#pragma unroll
    for (int t = 0; t < 2; t++) {
        if (warp_n == t) {
#pragma unroll
            for (int i = 0; i < 2; i++)
#pragma unroll
                for (int j = 0; j < 4; j++)
                    wmma::store_matrix_sync(&sm.buf[warp_m][i * 16][j * 16],
                                            c[i][j], 68, wmma::mem_row_major);
        }
        __syncthreads();
        for (int idx = tid; idx < 32 * 64; idx += NTHREADS) {
            int r = idx >> 6, cc = idx & 63;
            float s = sm.buf[0][r][cc] + sm.buf[1][r][cc] +
                      sm.buf[2][r][cc] + sm.buf[3][r][cc];
            float* dst = &g_part[b0 + r][n0 + t * 64 + cc];
            if (accumulate) s += *dst;   // branch 1: gates = part1 + part2
            *dst = s;
        }
        __syncthreads();
    }
}

// ---------------- fused gate / cell elementwise ----------------
__global__ void cell_kernel(const float* __restrict__ cx, float* __restrict__ out,
                            const float* a3, const float* a4, const float* a5,
                            const float* a6, const float* a7, const float* a8,
                            const float* a9, const float* a10, const float* a11) {
    int idx = blockIdx.x * blockDim.x + threadIdx.x;
    if (idx >= B_ * H_) return;
    int b = idx >> 10, h = idx & (H_ - 1);
    const float* row = &g_part[b][0];
    float gi = row[h];
    float gj = row[h + H_];
    float gf = row[h + 2 * H_];
    float go = row[h + 3 * H_];
    float v3 = *a3, v4 = *a4, v5 = *a5, v6 = *a6, v7 = *a7;
    float v8 = *a8, v9 = *a9, v10 = *a10, v11 = *a11;

    float fg  = qr8(pact_f(sigmoidf_(gf), v3), v3);
    float ig  = qr8(pact_f(sigmoidf_(gi), v4), v4);
    float act = qr8(pact_f(tanhf(gj),     v5), v5);
    float og  = qr8(pact_f(sigmoidf_(go), v6), v6);
    float gc  = qr8(pact_f(cx[idx] * fg,  v7), v7);
    float ai  = qr8(pact_f(ig * act,      v8), v8);
    float nc  = qr8(pact_f(gc + ai,       v9), v9);
    float ac  = qr8(pact_f(tanhf(nc),     v10), v10);
    float nh  = qr8(pact_f(ac * og,       v11), v11);

    out[idx]            = nh;   // new_h
    out[B_ * H_ + idx]  = nc;   // new_c
}

extern "C" void kernel_launch(void* const* d_in, const int* in_sizes, int n_in,
                              void* d_out, int out_size) {
    const float* input = (const float*)d_in[0];
    const float* hx    = (const float*)d_in[1];
    const float* cx    = (const float*)d_in[2];
    const float* wih   = (const float*)d_in[3];
    const float* whh   = (const float*)d_in[4];
    const float* bih   = (const float*)d_in[5];
    const float* bhh   = (const float*)d_in[6];
    const float* a1    = (const float*)d_in[7];
    const float* a3    = (const float*)d_in[8];
    const float* a4    = (const float*)d_in[9];
    const float* a5    = (const float*)d_in[10];
    const float* a6    = (const float*)d_in[11];
    const float* a7    = (const float*)d_in[12];
    const float* a8    = (const float*)d_in[13];
    const float* a9    = (const float*)d_in[14];
    const float* a10   = (const float*)d_in[15];
    const float* a11   = (const float*)d_in[16];
    float* out = (float*)d_out;

    quant_acts_kernel<<<(2 * B_ * K_ + 255) / 256, 256>>>(input, hx, a1, a11);
    quant_w_kernel<<<(2 * K_ * NG + 255) / 256, 256>>>(wih, whh, bih, bhh);

    dim3 grid(NG / BN, B_ / BROWS);
    gemm_kernel<<<grid, NTHREADS>>>(0, a1, 0);
    gemm_kernel<<<grid, NTHREADS>>>(1, a11, 1);

    cell_kernel<<<(B_ * H_ + 255) / 256, 256>>>(cx, out, a3, a4, a5, a6, a7,
                                                a8, a9, a10, a11);
}